// round 12
// baseline (speedup 1.0000x reference)
#include <cuda_runtime.h>
#include <math.h>
#include <cstdint>

#define NNODE  100000
#define CC     256
#define HEADS  8
#define NE     500000
#define NLAB   200000

#define MTILE  128
#define KC     32
#define NCHUNK 8
#define NBNP   8        // bnsum partitions

// ---------------- scratch (device globals; no allocations allowed) ----------
__device__ __align__(128) float g_h_req  [(size_t)NNODE * CC];
__device__ __align__(128) float g_h_code [(size_t)NNODE * CC];
__device__ __align__(128) float g_acc_req [(size_t)NNODE * CC];
__device__ __align__(128) float g_acc_code[(size_t)NNODE * CC];
__device__ __align__(128) float g_as_rc[NNODE * HEADS];
__device__ __align__(128) float g_ad_rc[NNODE * HEADS];
__device__ __align__(128) float g_as_cr[NNODE * HEADS];
__device__ __align__(128) float g_ad_cr[NNODE * HEADS];
__device__ __align__(128) float g_bnp[NBNP][1024]; // partitioned BN partials
__device__ __align__(128) float g_bn[1024];        // [which*512 + {scale, shift}]
// CSR scratch: type 0 = rc edges (dst=code), type 1 = cr edges (dst=req)
__device__ __align__(128) int g_deg [2][NNODE];
__device__ __align__(128) int g_offs[2][NNODE];
__device__ __align__(128) int g_cur [2][NNODE];
__device__ __align__(128) int g_srt [2][NE];
__device__ __align__(128) int g_cursor[4];

// ---------------- helpers ----------------------------------------------------
__device__ __forceinline__ uint32_t smem_to_u32(const void* p) {
    uint32_t a;
    asm("{ .reg .u64 t; cvta.to.shared.u64 t, %1; cvt.u32.u64 %0, t; }" : "=r"(a) : "l"(p));
    return a;
}
__device__ __forceinline__ uint32_t pack_bf16(float a, float b) {
    uint32_t r;
    asm("cvt.rn.bf16x2.f32 %0, %1, %2;" : "=r"(r) : "f"(b), "f"(a));
    return r;
}
__device__ __forceinline__ float bflo(uint32_t u) { return __uint_as_float(u << 16); }
__device__ __forceinline__ float bfhi(uint32_t u) { return __uint_as_float(u & 0xffff0000u); }

__device__ __forceinline__ void split_store(float4 v, char* hp, char* lp) {
    uint32_t h01 = pack_bf16(v.x, v.y);
    uint32_t h23 = pack_bf16(v.z, v.w);
    float l0 = v.x - bflo(h01), l1 = v.y - bfhi(h01);
    float l2 = v.z - bflo(h23), l3 = v.w - bfhi(h23);
    *(uint2*)hp = make_uint2(h01, h23);
    *(uint2*)lp = make_uint2(pack_bf16(l0, l1), pack_bf16(l2, l3));
}

#define LDSM_X4(R, ADDR) \
    asm volatile("ldmatrix.sync.aligned.m8n8.x4.shared.b16 {%0,%1,%2,%3}, [%4];" \
        : "=r"((R)[0]), "=r"((R)[1]), "=r"((R)[2]), "=r"((R)[3]) : "r"(ADDR))

__device__ __forceinline__ void mma16816(float* d, const uint32_t* a, const uint32_t* b) {
    asm volatile("mma.sync.aligned.m16n8k16.row.col.f32.bf16.bf16.f32 "
        "{%0,%1,%2,%3}, {%4,%5,%6,%7}, {%8,%9}, {%0,%1,%2,%3};"
        : "+f"(d[0]), "+f"(d[1]), "+f"(d[2]), "+f"(d[3])
        : "r"(a[0]), "r"(a[1]), "r"(a[2]), "r"(a[3]), "r"(b[0]), "r"(b[1]));
}

__device__ __forceinline__ void red4(float* p, float4 v) {
    asm volatile("red.global.add.v4.f32 [%0], {%1,%2,%3,%4};"
                 :: "l"(p), "f"(v.x), "f"(v.y), "f"(v.z), "f"(v.w) : "memory");
}

// ---------------- zero fill --------------------------------------------------
__global__ __launch_bounds__(256) void k_zero(float4* p, int n4) {
    int i = blockIdx.x * 256 + threadIdx.x;
    if (i < n4) p[i] = make_float4(0.f, 0.f, 0.f, 0.f);
}

// ---------------- bf16x3 mma GEMM + fused bias + attention dots --------------
#define ROWB      80
#define SM_BIAS   0
#define SM_ATTA   1024
#define SM_ATTB   2048
#define SM_TILE   3072
#define ST_A_HI   0
#define ST_A_LO   10240
#define ST_B_HI   20480
#define ST_B_LO   40960
#define STAGE_BYTES 61440
#define SMEM_GEMM_TOTAL (SM_TILE + 2 * STAGE_BYTES)   // 125952

struct GemmArgs {
    const float* X; const float* W; const float* bias;
    float* H; const float* attA; const float* attB;
    float* outA; float* outB;
};

__global__ void __launch_bounds__(512, 1) k_gemm_mma(GemmArgs g0, GemmArgs g1)
{
    extern __shared__ char smem[];
    const GemmArgs g = blockIdx.y ? g1 : g0;
    const int t = threadIdx.x;
    const int lane = t & 31;
    const int wid = t >> 5;
    const int wm = wid >> 2;
    const int wn = wid & 3;
    const int rbase = blockIdx.x * MTILE;

    if (t < 256) {
        ((float*)(smem + SM_BIAS))[t] = g.bias[t];
        ((float*)(smem + SM_ATTA))[t] = g.attA[t];
        ((float*)(smem + SM_ATTB))[t] = g.attB[t];
    }

    float4 pa[2], pb[4];

#define LOAD_REGS(c) do { \
    for (int i = 0; i < 2; i++) { \
        int idx = t + 512 * i; int row = idx >> 3, f = idx & 7; \
        int gr = rbase + row; \
        pa[i] = (gr < NNODE) \
            ? *(const float4*)(g.X + (size_t)gr * CC + (c) * KC + f * 4) \
            : make_float4(0.f, 0.f, 0.f, 0.f); \
    } \
    for (int i = 0; i < 4; i++) { \
        int idx = t + 512 * i; int row = idx >> 3, f = idx & 7; \
        pb[i] = *(const float4*)(g.W + (size_t)row * CC + (c) * KC + f * 4); \
    } } while (0)

#define STORE_REGS(s) do { \
    char* base = smem + SM_TILE + (s) * STAGE_BYTES; \
    for (int i = 0; i < 2; i++) { \
        int idx = t + 512 * i; int row = idx >> 3, f = idx & 7; \
        split_store(pa[i], base + ST_A_HI + row * ROWB + f * 8, \
                           base + ST_A_LO + row * ROWB + f * 8); \
    } \
    for (int i = 0; i < 4; i++) { \
        int idx = t + 512 * i; int row = idx >> 3, f = idx & 7; \
        split_store(pb[i], base + ST_B_HI + row * ROWB + f * 8, \
                           base + ST_B_LO + row * ROWB + f * 8); \
    } } while (0)

    float acc[2][8][4];
#pragma unroll
    for (int a = 0; a < 2; a++)
#pragma unroll
        for (int b = 0; b < 8; b++)
#pragma unroll
            for (int k = 0; k < 4; k++) acc[a][b][k] = 0.f;

    LOAD_REGS(0);
    STORE_REGS(0);
    LOAD_REGS(1);

    const uint32_t sbase = smem_to_u32(smem) + SM_TILE;
    const uint32_t a_lane_off = (uint32_t)((lane & 15) * ROWB + (lane >> 4) * 16);
    const uint32_t b_lane_off = (uint32_t)(((lane & 7) + ((lane >> 4) & 1) * 8) * ROWB
                                           + ((lane >> 3) & 1) * 16);

    for (int c = 0; c < NCHUNK; c++) {
        const int b = c & 1;
        __syncthreads();
        if (c + 1 < NCHUNK) STORE_REGS(b ^ 1);
        __syncthreads();
        if (c + 2 < NCHUNK) LOAD_REGS(c + 2);
        const uint32_t stg = sbase + (uint32_t)b * STAGE_BYTES;
#pragma unroll
        for (int ks = 0; ks < 2; ks++) {
            uint32_t ahi[2][4], alo[2][4];
            uint32_t a_base = stg + ST_A_HI + (uint32_t)(wm * 32 * ROWB) + ks * 32 + a_lane_off;
            LDSM_X4(ahi[0], a_base);
            LDSM_X4(ahi[1], a_base + 16 * ROWB);
            LDSM_X4(alo[0], a_base + (ST_A_LO - ST_A_HI));
            LDSM_X4(alo[1], a_base + (ST_A_LO - ST_A_HI) + 16 * ROWB);
            uint32_t b_base = stg + ST_B_HI + (uint32_t)(wn * 64 * ROWB) + ks * 32 + b_lane_off;
#pragma unroll
            for (int np = 0; np < 4; np++) {
                uint32_t bh[4], bl[4];
                LDSM_X4(bh, b_base + np * 16 * ROWB);
                LDSM_X4(bl, b_base + np * 16 * ROWB + (ST_B_LO - ST_B_HI));
#pragma unroll
                for (int mt = 0; mt < 2; mt++) {
                    mma16816(acc[mt][2 * np],     ahi[mt], bh);
                    mma16816(acc[mt][2 * np],     alo[mt], bh);
                    mma16816(acc[mt][2 * np],     ahi[mt], bl);
                    mma16816(acc[mt][2 * np + 1], ahi[mt], bh + 2);
                    mma16816(acc[mt][2 * np + 1], alo[mt], bh + 2);
                    mma16816(acc[mt][2 * np + 1], ahi[mt], bl + 2);
                }
            }
        }
    }

    const float* bias = (const float*)(smem + SM_BIAS);
    const float* aA = (const float*)(smem + SM_ATTA);
    const float* aB = (const float*)(smem + SM_ATTB);
    const int g4 = lane >> 2, q = lane & 3;
#pragma unroll
    for (int mt = 0; mt < 2; mt++) {
#pragma unroll
        for (int half = 0; half < 2; half++) {
            const int row = rbase + wm * 32 + mt * 16 + g4 + 8 * half;
            const bool ok = row < NNODE;
            float dA0 = 0.f, dA1 = 0.f, dB0 = 0.f, dB1 = 0.f;
#pragma unroll
            for (int nt = 0; nt < 8; nt++) {
                const int c0 = wn * 64 + nt * 8 + q * 2;
                float v0 = acc[mt][nt][2 * half + 0] + bias[c0];
                float v1 = acc[mt][nt][2 * half + 1] + bias[c0 + 1];
                if (ok) *(float2*)(g.H + (size_t)row * CC + c0) = make_float2(v0, v1);
                float da = v0 * aA[c0] + v1 * aA[c0 + 1];
                float db = v0 * aB[c0] + v1 * aB[c0 + 1];
                if (nt < 4) { dA0 += da; dB0 += db; }
                else        { dA1 += da; dB1 += db; }
            }
#pragma unroll
            for (int o = 1; o < 4; o <<= 1) {
                dA0 += __shfl_xor_sync(0xffffffffu, dA0, o);
                dA1 += __shfl_xor_sync(0xffffffffu, dA1, o);
                dB0 += __shfl_xor_sync(0xffffffffu, dB0, o);
                dB1 += __shfl_xor_sync(0xffffffffu, dB1, o);
            }
            if (q == 0 && ok) {
                const int hb = row * 8 + wn * 2;
                g.outA[hb]     = dA0;
                g.outA[hb + 1] = dA1;
                g.outB[hb]     = dB0;
                g.outB[hb + 1] = dB1;
            }
        }
    }
#undef LOAD_REGS
#undef STORE_REGS
}

// ---------------- CSR build: histogram, block-alloc, permute ------------------
__global__ __launch_bounds__(256) void k_hist(const int* e0, const int* e1) {
    int i = blockIdx.x * 256 + threadIdx.x;
    if (i >= NE) return;
    if (blockIdx.y == 0) atomicAdd(&g_deg[0][e0[NE + i]], 1);
    else                 atomicAdd(&g_deg[1][e1[NE + i]], 1);
}

__global__ __launch_bounds__(256) void k_alloc() {
    const int ty = blockIdx.y;
    const int i = blockIdx.x * 256 + threadIdx.x;
    const int lane = threadIdx.x & 31, wid = threadIdx.x >> 5;
    int v = (i < NNODE) ? g_deg[ty][i] : 0;
    int x = v;
#pragma unroll
    for (int o = 1; o < 32; o <<= 1) {
        int y = __shfl_up_sync(0xffffffffu, x, o);
        if (lane >= o) x += y;
    }
    __shared__ int wtot[8];
    __shared__ int bbase;
    if (lane == 31) wtot[wid] = x;
    __syncthreads();
    if (threadIdx.x == 0) {
        int r = 0;
#pragma unroll
        for (int w = 0; w < 8; w++) { int tmp = wtot[w]; wtot[w] = r; r += tmp; }
        bbase = atomicAdd(&g_cursor[ty], r);
    }
    __syncthreads();
    if (i < NNODE) {
        int excl = bbase + wtot[wid] + x - v;
        g_offs[ty][i] = excl;
        g_cur[ty][i]  = excl;
    }
}

__global__ __launch_bounds__(256) void k_permute(const int* e0, const int* e1) {
    int i = blockIdx.x * 256 + threadIdx.x;
    if (i >= NE) return;
    int ty = blockIdx.y;
    const int* e = ty ? e1 : e0;
    int src = e[i], dst = e[NE + i];
    int pos = atomicAdd(&g_cur[ty][dst], 1);
    g_srt[ty][pos] = src;
}

// ---------------- CSR aggregate ------------------------------------------------
// 2 warps per dst (half-row each), 4-edge batched prefetch for MLP.
// Fuses segment-softmax divide + relu + acc store + BN partial sums.
struct AggArgs {
    const float* a_s; const float* a_d; const float* h; float* acc; int bnoff;
};

__global__ __launch_bounds__(256) void k_agg(AggArgs a0, AggArgs a1)
{
    const int ty = blockIdx.y;
    const AggArgs A = ty ? a1 : a0;
    const int wid = threadIdx.x >> 5;
    const int lane = threadIdx.x & 31;
    const int dst = blockIdx.x * 4 + (wid >> 1);
    const int half = wid & 1;
    const int myhead = half * 4 + (lane >> 3);

    const int n = g_deg[ty][dst];
    const int start = g_offs[ty][dst];
    const int* srt = g_srt[ty];

    const float ad_v = (lane < 8) ? A.a_d[dst * 8 + lane] : 0.f;
    float ssum = 0.f;
    float4 acc = make_float4(0.f, 0.f, 0.f, 0.f);
    const float* hbase = A.h + half * 128 + 4 * lane;

    for (int k0 = 0; k0 < n; k0 += 4) {
        float4 m[4];
        float asv[4];
#pragma unroll
        for (int j = 0; j < 4; j++) {
            if (k0 + j < n) {
                int s = srt[start + k0 + j];
                m[j] = *(const float4*)(hbase + (size_t)s * CC);
                asv[j] = (lane < 8) ? A.a_s[s * 8 + lane] : 0.f;
            }
        }
#pragma unroll
        for (int j = 0; j < 4; j++) {
            if (k0 + j < n) {
                float ev = 0.f;
                if (lane < 8) {
                    float l = asv[j] + ad_v;
                    l = (l > 0.f) ? l : 0.2f * l;
                    ev = __expf(l);
                    ssum += ev;
                }
                float w = __shfl_sync(0xffffffffu, ev, myhead);
                acc.x += w * m[j].x; acc.y += w * m[j].y;
                acc.z += w * m[j].z; acc.w += w * m[j].w;
            }
        }
    }
    float inv = 1.f / (__shfl_sync(0xffffffffu, ssum, myhead) + 1e-16f);
    float4 v;
    v.x = fmaxf(acc.x * inv, 0.f); v.y = fmaxf(acc.y * inv, 0.f);
    v.z = fmaxf(acc.z * inv, 0.f); v.w = fmaxf(acc.w * inv, 0.f);
    *(float4*)(A.acc + (size_t)dst * CC + half * 128 + 4 * lane) = v;

    // BN partial sums: smem-reduce the warps, then red.v4 into partitioned bins
    __shared__ float4 sm[2][8][32];
    sm[0][wid][lane] = v;
    sm[1][wid][lane] = make_float4(v.x * v.x, v.y * v.y, v.z * v.z, v.w * v.w);
    __syncthreads();
    if (threadIdx.x < 128) {
        const int a  = threadIdx.x >> 6;        // 0 sum, 1 sumsq
        const int hh = (threadIdx.x >> 5) & 1;  // half
        const int l  = threadIdx.x & 31;
        float4 r = make_float4(0.f, 0.f, 0.f, 0.f);
#pragma unroll
        for (int w = hh; w < 8; w += 2) {
            float4 u = sm[a][w][l];
            r.x += u.x; r.y += u.y; r.z += u.z; r.w += u.w;
        }
        float* bp = &g_bnp[blockIdx.x & (NBNP - 1)]
                          [A.bnoff + a * 256 + hh * 128 + 4 * l];
        red4(bp, r);
    }
}

// ---------------- BN stats -> per-channel affine -----------------------------
__global__ __launch_bounds__(512) void k_bnstats(
    const float* __restrict__ gamma, const float* __restrict__ beta)
{
    int t = threadIdx.x;
    int c = t & 255;
    int which = t >> 8;
    float sum = 0.f, sq = 0.f;
#pragma unroll
    for (int p = 0; p < NBNP; p++) {
        sum += g_bnp[p][which * 512 + c];
        sq  += g_bnp[p][which * 512 + 256 + c];
    }
    const float invN = 1.f / 100000.f;
    float mean = sum * invN;
    float var  = sq * invN - mean * mean;
    float scale = gamma[c] * rsqrtf(var + 1e-5f);
    g_bn[which * 512 + c]       = scale;
    g_bn[which * 512 + 256 + c] = beta[c] - mean * scale;
}

// ---------------- classifier --------------------------------------------------
__global__ __launch_bounds__(256) void k_classify(
    const int* __restrict__ eli, float* __restrict__ out)
{
    __shared__ float bn[1024];
    int t = threadIdx.x;
#pragma unroll
    for (int k = 0; k < 4; k++) bn[t + 256 * k] = g_bn[t + 256 * k];
    __syncthreads();
    int e = blockIdx.x * 8 + (t >> 5);
    int lane = t & 31;
    if (e >= NLAB) return;
    int i = eli[e];
    int j = eli[NLAB + e];
    const float4* zr = (const float4*)(g_acc_req + (size_t)i * CC);
    const float4* zc = (const float4*)(g_acc_code + (size_t)j * CC);
    float4 a0 = zr[lane], a1 = zr[lane + 32];
    float4 b0 = zc[lane], b1 = zc[lane + 32];
    int c0 = 4 * lane, c1 = 128 + 4 * lane;
    float dot = 0.f;
#pragma unroll
    for (int k = 0; k < 4; k++) {
        float ya = (&a0.x)[k] * bn[c0 + k] + bn[256 + c0 + k];
        float yb = (&b0.x)[k] * bn[512 + c0 + k] + bn[768 + c0 + k];
        dot += ya * yb;
    }
#pragma unroll
    for (int k = 0; k < 4; k++) {
        float ya = (&a1.x)[k] * bn[c1 + k] + bn[256 + c1 + k];
        float yb = (&b1.x)[k] * bn[512 + c1 + k] + bn[768 + c1 + k];
        dot += ya * yb;
    }
#pragma unroll
    for (int o = 16; o >= 1; o >>= 1) dot += __shfl_xor_sync(0xffffffffu, dot, o);
    if (lane == 0) out[e] = 1.f / (1.f + __expf(-dot));
}

// ---------------- host -------------------------------------------------------
template <class T>
static T* getsym(const void* sym) {
    void* p = nullptr;
    cudaGetSymbolAddress(&p, sym);
    return (T*)p;
}

extern "C" void kernel_launch(void* const* d_in, const int* in_sizes, int n_in,
                              void* d_out, int out_size)
{
    const float* x_req      = (const float*)d_in[0];
    const float* x_code     = (const float*)d_in[1];
    const int*   e_rc       = (const int*)d_in[2];
    const int*   e_cr       = (const int*)d_in[3];
    const int*   eli        = (const int*)d_in[4];
    const float* W_req      = (const float*)d_in[5];
    const float* b_req      = (const float*)d_in[6];
    const float* W_code     = (const float*)d_in[7];
    const float* b_code     = (const float*)d_in[8];
    const float* att_src_rc = (const float*)d_in[9];
    const float* att_dst_rc = (const float*)d_in[10];
    const float* att_src_cr = (const float*)d_in[11];
    const float* att_dst_cr = (const float*)d_in[12];
    // d_in[13..15] (k_W, k_b, q) are dead: semantic attention over one metapath.
    const float* gamma      = (const float*)d_in[16];
    const float* beta       = (const float*)d_in[17];
    float* out = (float*)d_out;

    float* h_req    = getsym<float>(g_h_req);
    float* h_code   = getsym<float>(g_h_code);
    float* acc_req  = getsym<float>(g_acc_req);
    float* acc_code = getsym<float>(g_acc_code);
    float* as_rc    = getsym<float>(g_as_rc);
    float* ad_rc    = getsym<float>(g_ad_rc);
    float* as_cr    = getsym<float>(g_as_cr);
    float* ad_cr    = getsym<float>(g_ad_cr);
    float* deg      = getsym<float>(g_deg);
    float* bnp      = getsym<float>(g_bnp);
    float* cursor   = getsym<float>(g_cursor);

    // ---- fork a non-blocking side stream for the CSR build (runs under GEMM).
    // kernel_launch is invoked only for the correctness run + graph capture, so
    // creating (and intentionally not destroying) these handles is cheap and
    // keeps per-call work identical. NonBlocking exempts the side stream from
    // legacy-stream implicit sync; event fork/join makes the capture a DAG.
    cudaStream_t s2;
    cudaEvent_t evFork, evJoin;
    cudaStreamCreateWithFlags(&s2, cudaStreamNonBlocking);
    cudaEventCreateWithFlags(&evFork, cudaEventDisableTiming);
    cudaEventCreateWithFlags(&evJoin, cudaEventDisableTiming);

    cudaEventRecord(evFork, 0);
    cudaStreamWaitEvent(s2, evFork, 0);

    // ---- side stream: zero deg/cursor + CSR build ----
    k_zero<<<(2 * NNODE / 4 + 255) / 256, 256, 0, s2>>>((float4*)deg, 2 * NNODE / 4);
    k_zero<<<1, 256, 0, s2>>>((float4*)cursor, 1);
    dim3 hgrid((NE + 255) / 256, 2);
    k_hist<<<hgrid, 256, 0, s2>>>(e_rc, e_cr);
    dim3 agrid2((NNODE + 255) / 256, 2);
    k_alloc<<<agrid2, 256, 0, s2>>>();
    k_permute<<<hgrid, 256, 0, s2>>>(e_rc, e_cr);
    cudaEventRecord(evJoin, s2);

    // ---- main stream: bnp zero + bf16x3 tensor-core projections ----
    k_zero<<<(NBNP * 1024 / 4 + 255) / 256, 256>>>((float4*)bnp, NBNP * 1024 / 4);

    GemmArgs gr{ x_req,  W_req,  b_req,  h_req,  att_src_rc, att_dst_cr, as_rc, ad_cr };
    GemmArgs gc{ x_code, W_code, b_code, h_code, att_dst_rc, att_src_cr, ad_rc, as_cr };
    cudaFuncSetAttribute(k_gemm_mma, cudaFuncAttributeMaxDynamicSharedMemorySize,
                         SMEM_GEMM_TOTAL);
    dim3 ggrid((NNODE + MTILE - 1) / MTILE, 2);
    k_gemm_mma<<<ggrid, 512, SMEM_GEMM_TOTAL>>>(gr, gc);

    // ---- join: agg needs both CSR (side) and h/attdots (main) ----
    cudaStreamWaitEvent(0, evJoin, 0);

    // ---- CSR aggregate (2 warps/dst, batched prefetch, both types concurrent) ----
    AggArgs a0{ as_rc, ad_rc, h_req,  acc_code, 512 };
    AggArgs a1{ as_cr, ad_cr, h_code, acc_req,  0   };
    dim3 agrid(NNODE / 4, 2);
    k_agg<<<agrid, 256>>>(a0, a1);

    k_bnstats<<<1, 512>>>(gamma, beta);

    k_classify<<<(NLAB + 7) / 8, 256>>>(eli, out);
}

// round 14
// speedup vs baseline: 1.0027x; 1.0027x over previous
#include <cuda_runtime.h>
#include <math.h>
#include <cstdint>

#define NNODE  100000
#define CC     256
#define HEADS  8
#define NE     500000
#define NLAB   200000

#define MTILE  128
#define KC     32
#define NCHUNK 8
#define NBNP   8        // bnsum partitions

// ---------------- scratch (device globals; no allocations allowed) ----------
__device__ __align__(128) float g_h_req  [(size_t)NNODE * CC];
__device__ __align__(128) float g_h_code [(size_t)NNODE * CC];
__device__ __align__(128) float g_acc_req [(size_t)NNODE * CC];
__device__ __align__(128) float g_acc_code[(size_t)NNODE * CC];
__device__ __align__(128) float g_as_rc[NNODE * HEADS];
__device__ __align__(128) float g_ad_rc[NNODE * HEADS];
__device__ __align__(128) float g_as_cr[NNODE * HEADS];
__device__ __align__(128) float g_ad_cr[NNODE * HEADS];
__device__ __align__(128) float g_bnp[NBNP][1024]; // partitioned BN partials
__device__ __align__(128) float g_bn[1024];        // [which*512 + {scale, shift}]
// CSR scratch: type 0 = rc edges (dst=code), type 1 = cr edges (dst=req)
__device__ __align__(128) int g_deg [2][NNODE];
__device__ __align__(128) int g_offs[2][NNODE];
__device__ __align__(128) int g_cur [2][NNODE];
__device__ __align__(128) int g_srt [2][NE];
__device__ __align__(128) int g_cursor[4];

// ---------------- helpers ----------------------------------------------------
__device__ __forceinline__ uint32_t smem_to_u32(const void* p) {
    uint32_t a;
    asm("{ .reg .u64 t; cvta.to.shared.u64 t, %1; cvt.u32.u64 %0, t; }" : "=r"(a) : "l"(p));
    return a;
}
__device__ __forceinline__ uint32_t pack_bf16(float a, float b) {
    uint32_t r;
    asm("cvt.rn.bf16x2.f32 %0, %1, %2;" : "=r"(r) : "f"(b), "f"(a));
    return r;
}
__device__ __forceinline__ float bflo(uint32_t u) { return __uint_as_float(u << 16); }
__device__ __forceinline__ float bfhi(uint32_t u) { return __uint_as_float(u & 0xffff0000u); }

__device__ __forceinline__ void split_store(float4 v, char* hp, char* lp) {
    uint32_t h01 = pack_bf16(v.x, v.y);
    uint32_t h23 = pack_bf16(v.z, v.w);
    float l0 = v.x - bflo(h01), l1 = v.y - bfhi(h01);
    float l2 = v.z - bflo(h23), l3 = v.w - bfhi(h23);
    *(uint2*)hp = make_uint2(h01, h23);
    *(uint2*)lp = make_uint2(pack_bf16(l0, l1), pack_bf16(l2, l3));
}

#define LDSM_X4(R, ADDR) \
    asm volatile("ldmatrix.sync.aligned.m8n8.x4.shared.b16 {%0,%1,%2,%3}, [%4];" \
        : "=r"((R)[0]), "=r"((R)[1]), "=r"((R)[2]), "=r"((R)[3]) : "r"(ADDR))

__device__ __forceinline__ void mma16816(float* d, const uint32_t* a, const uint32_t* b) {
    asm volatile("mma.sync.aligned.m16n8k16.row.col.f32.bf16.bf16.f32 "
        "{%0,%1,%2,%3}, {%4,%5,%6,%7}, {%8,%9}, {%0,%1,%2,%3};"
        : "+f"(d[0]), "+f"(d[1]), "+f"(d[2]), "+f"(d[3])
        : "r"(a[0]), "r"(a[1]), "r"(a[2]), "r"(a[3]), "r"(b[0]), "r"(b[1]));
}

__device__ __forceinline__ void red4(float* p, float4 v) {
    asm volatile("red.global.add.v4.f32 [%0], {%1,%2,%3,%4};"
                 :: "l"(p), "f"(v.x), "f"(v.y), "f"(v.z), "f"(v.w) : "memory");
}

// ---------------- zero fill --------------------------------------------------
__global__ __launch_bounds__(256) void k_zero(float4* p, int n4) {
    int i = blockIdx.x * 256 + threadIdx.x;
    if (i < n4) p[i] = make_float4(0.f, 0.f, 0.f, 0.f);
}

// ---------------- bf16x3 mma GEMM + fused bias + attention dots --------------
#define ROWB      80
#define SM_BIAS   0
#define SM_ATTA   1024
#define SM_ATTB   2048
#define SM_TILE   3072
#define ST_A_HI   0
#define ST_A_LO   10240
#define ST_B_HI   20480
#define ST_B_LO   40960
#define STAGE_BYTES 61440
#define SMEM_GEMM_TOTAL (SM_TILE + 2 * STAGE_BYTES)   // 125952

struct GemmArgs {
    const float* X; const float* W; const float* bias;
    float* H; const float* attA; const float* attB;
    float* outA; float* outB;
};

__global__ void __launch_bounds__(512, 1) k_gemm_mma(GemmArgs g0, GemmArgs g1)
{
    extern __shared__ char smem[];
    const GemmArgs g = blockIdx.y ? g1 : g0;
    const int t = threadIdx.x;
    const int lane = t & 31;
    const int wid = t >> 5;
    const int wm = wid >> 2;
    const int wn = wid & 3;
    const int rbase = blockIdx.x * MTILE;

    if (t < 256) {
        ((float*)(smem + SM_BIAS))[t] = g.bias[t];
        ((float*)(smem + SM_ATTA))[t] = g.attA[t];
        ((float*)(smem + SM_ATTB))[t] = g.attB[t];
    }

    float4 pa[2], pb[4];

#define LOAD_REGS(c) do { \
    for (int i = 0; i < 2; i++) { \
        int idx = t + 512 * i; int row = idx >> 3, f = idx & 7; \
        int gr = rbase + row; \
        pa[i] = (gr < NNODE) \
            ? *(const float4*)(g.X + (size_t)gr * CC + (c) * KC + f * 4) \
            : make_float4(0.f, 0.f, 0.f, 0.f); \
    } \
    for (int i = 0; i < 4; i++) { \
        int idx = t + 512 * i; int row = idx >> 3, f = idx & 7; \
        pb[i] = *(const float4*)(g.W + (size_t)row * CC + (c) * KC + f * 4); \
    } } while (0)

#define STORE_REGS(s) do { \
    char* base = smem + SM_TILE + (s) * STAGE_BYTES; \
    for (int i = 0; i < 2; i++) { \
        int idx = t + 512 * i; int row = idx >> 3, f = idx & 7; \
        split_store(pa[i], base + ST_A_HI + row * ROWB + f * 8, \
                           base + ST_A_LO + row * ROWB + f * 8); \
    } \
    for (int i = 0; i < 4; i++) { \
        int idx = t + 512 * i; int row = idx >> 3, f = idx & 7; \
        split_store(pb[i], base + ST_B_HI + row * ROWB + f * 8, \
                           base + ST_B_LO + row * ROWB + f * 8); \
    } } while (0)

    float acc[2][8][4];
#pragma unroll
    for (int a = 0; a < 2; a++)
#pragma unroll
        for (int b = 0; b < 8; b++)
#pragma unroll
            for (int k = 0; k < 4; k++) acc[a][b][k] = 0.f;

    LOAD_REGS(0);
    STORE_REGS(0);
    LOAD_REGS(1);

    const uint32_t sbase = smem_to_u32(smem) + SM_TILE;
    const uint32_t a_lane_off = (uint32_t)((lane & 15) * ROWB + (lane >> 4) * 16);
    const uint32_t b_lane_off = (uint32_t)(((lane & 7) + ((lane >> 4) & 1) * 8) * ROWB
                                           + ((lane >> 3) & 1) * 16);

    for (int c = 0; c < NCHUNK; c++) {
        const int b = c & 1;
        __syncthreads();
        if (c + 1 < NCHUNK) STORE_REGS(b ^ 1);
        __syncthreads();
        if (c + 2 < NCHUNK) LOAD_REGS(c + 2);
        const uint32_t stg = sbase + (uint32_t)b * STAGE_BYTES;
#pragma unroll
        for (int ks = 0; ks < 2; ks++) {
            uint32_t ahi[2][4], alo[2][4];
            uint32_t a_base = stg + ST_A_HI + (uint32_t)(wm * 32 * ROWB) + ks * 32 + a_lane_off;
            LDSM_X4(ahi[0], a_base);
            LDSM_X4(ahi[1], a_base + 16 * ROWB);
            LDSM_X4(alo[0], a_base + (ST_A_LO - ST_A_HI));
            LDSM_X4(alo[1], a_base + (ST_A_LO - ST_A_HI) + 16 * ROWB);
            uint32_t b_base = stg + ST_B_HI + (uint32_t)(wn * 64 * ROWB) + ks * 32 + b_lane_off;
#pragma unroll
            for (int np = 0; np < 4; np++) {
                uint32_t bh[4], bl[4];
                LDSM_X4(bh, b_base + np * 16 * ROWB);
                LDSM_X4(bl, b_base + np * 16 * ROWB + (ST_B_LO - ST_B_HI));
#pragma unroll
                for (int mt = 0; mt < 2; mt++) {
                    mma16816(acc[mt][2 * np],     ahi[mt], bh);
                    mma16816(acc[mt][2 * np],     alo[mt], bh);
                    mma16816(acc[mt][2 * np],     ahi[mt], bl);
                    mma16816(acc[mt][2 * np + 1], ahi[mt], bh + 2);
                    mma16816(acc[mt][2 * np + 1], alo[mt], bh + 2);
                    mma16816(acc[mt][2 * np + 1], ahi[mt], bl + 2);
                }
            }
        }
    }

    const float* bias = (const float*)(smem + SM_BIAS);
    const float* aA = (const float*)(smem + SM_ATTA);
    const float* aB = (const float*)(smem + SM_ATTB);
    const int g4 = lane >> 2, q = lane & 3;
#pragma unroll
    for (int mt = 0; mt < 2; mt++) {
#pragma unroll
        for (int half = 0; half < 2; half++) {
            const int row = rbase + wm * 32 + mt * 16 + g4 + 8 * half;
            const bool ok = row < NNODE;
            float dA0 = 0.f, dA1 = 0.f, dB0 = 0.f, dB1 = 0.f;
#pragma unroll
            for (int nt = 0; nt < 8; nt++) {
                const int c0 = wn * 64 + nt * 8 + q * 2;
                float v0 = acc[mt][nt][2 * half + 0] + bias[c0];
                float v1 = acc[mt][nt][2 * half + 1] + bias[c0 + 1];
                if (ok) *(float2*)(g.H + (size_t)row * CC + c0) = make_float2(v0, v1);
                float da = v0 * aA[c0] + v1 * aA[c0 + 1];
                float db = v0 * aB[c0] + v1 * aB[c0 + 1];
                if (nt < 4) { dA0 += da; dB0 += db; }
                else        { dA1 += da; dB1 += db; }
            }
#pragma unroll
            for (int o = 1; o < 4; o <<= 1) {
                dA0 += __shfl_xor_sync(0xffffffffu, dA0, o);
                dA1 += __shfl_xor_sync(0xffffffffu, dA1, o);
                dB0 += __shfl_xor_sync(0xffffffffu, dB0, o);
                dB1 += __shfl_xor_sync(0xffffffffu, dB1, o);
            }
            if (q == 0 && ok) {
                const int hb = row * 8 + wn * 2;
                g.outA[hb]     = dA0;
                g.outA[hb + 1] = dA1;
                g.outB[hb]     = dB0;
                g.outB[hb + 1] = dB1;
            }
        }
    }
#undef LOAD_REGS
#undef STORE_REGS
}

// ---------------- CSR build: histogram, block-alloc, permute ------------------
__global__ __launch_bounds__(256) void k_hist(const int* e0, const int* e1) {
    int i = blockIdx.x * 256 + threadIdx.x;
    if (i >= NE) return;
    if (blockIdx.y == 0) atomicAdd(&g_deg[0][e0[NE + i]], 1);
    else                 atomicAdd(&g_deg[1][e1[NE + i]], 1);
}

__global__ __launch_bounds__(256) void k_alloc() {
    const int ty = blockIdx.y;
    const int i = blockIdx.x * 256 + threadIdx.x;
    const int lane = threadIdx.x & 31, wid = threadIdx.x >> 5;
    int v = (i < NNODE) ? g_deg[ty][i] : 0;
    int x = v;
#pragma unroll
    for (int o = 1; o < 32; o <<= 1) {
        int y = __shfl_up_sync(0xffffffffu, x, o);
        if (lane >= o) x += y;
    }
    __shared__ int wtot[8];
    __shared__ int bbase;
    if (lane == 31) wtot[wid] = x;
    __syncthreads();
    if (threadIdx.x == 0) {
        int r = 0;
#pragma unroll
        for (int w = 0; w < 8; w++) { int tmp = wtot[w]; wtot[w] = r; r += tmp; }
        bbase = atomicAdd(&g_cursor[ty], r);
    }
    __syncthreads();
    if (i < NNODE) {
        int excl = bbase + wtot[wid] + x - v;
        g_offs[ty][i] = excl;
        g_cur[ty][i]  = excl;
    }
}

__global__ __launch_bounds__(256) void k_permute(const int* e0, const int* e1) {
    int i = blockIdx.x * 256 + threadIdx.x;
    if (i >= NE) return;
    int ty = blockIdx.y;
    const int* e = ty ? e1 : e0;
    int src = e[i], dst = e[NE + i];
    int pos = atomicAdd(&g_cur[ty][dst], 1);
    g_srt[ty][pos] = src;
}

// ---------------- CSR aggregate ------------------------------------------------
// 2 warps per dst (half-row each), 4-edge batched prefetch for MLP.
// Fuses segment-softmax divide + relu + acc store + BN partial sums.
struct AggArgs {
    const float* a_s; const float* a_d; const float* h; float* acc; int bnoff;
};

__global__ __launch_bounds__(256) void k_agg(AggArgs a0, AggArgs a1)
{
    const int ty = blockIdx.y;
    const AggArgs A = ty ? a1 : a0;
    const int wid = threadIdx.x >> 5;
    const int lane = threadIdx.x & 31;
    const int dst = blockIdx.x * 4 + (wid >> 1);
    const int half = wid & 1;
    const int myhead = half * 4 + (lane >> 3);

    const int n = g_deg[ty][dst];
    const int start = g_offs[ty][dst];
    const int* srt = g_srt[ty];

    const float ad_v = (lane < 8) ? A.a_d[dst * 8 + lane] : 0.f;
    float ssum = 0.f;
    float4 acc = make_float4(0.f, 0.f, 0.f, 0.f);
    const float* hbase = A.h + half * 128 + 4 * lane;

    for (int k0 = 0; k0 < n; k0 += 4) {
        float4 m[4];
        float asv[4];
#pragma unroll
        for (int j = 0; j < 4; j++) {
            if (k0 + j < n) {
                int s = srt[start + k0 + j];
                m[j] = *(const float4*)(hbase + (size_t)s * CC);
                asv[j] = (lane < 8) ? A.a_s[s * 8 + lane] : 0.f;
            }
        }
#pragma unroll
        for (int j = 0; j < 4; j++) {
            if (k0 + j < n) {
                float ev = 0.f;
                if (lane < 8) {
                    float l = asv[j] + ad_v;
                    l = (l > 0.f) ? l : 0.2f * l;
                    ev = __expf(l);
                    ssum += ev;
                }
                float w = __shfl_sync(0xffffffffu, ev, myhead);
                acc.x += w * m[j].x; acc.y += w * m[j].y;
                acc.z += w * m[j].z; acc.w += w * m[j].w;
            }
        }
    }
    float inv = 1.f / (__shfl_sync(0xffffffffu, ssum, myhead) + 1e-16f);
    float4 v;
    v.x = fmaxf(acc.x * inv, 0.f); v.y = fmaxf(acc.y * inv, 0.f);
    v.z = fmaxf(acc.z * inv, 0.f); v.w = fmaxf(acc.w * inv, 0.f);
    *(float4*)(A.acc + (size_t)dst * CC + half * 128 + 4 * lane) = v;

    // BN partial sums: smem-reduce the warps, then red.v4 into partitioned bins
    __shared__ float4 sm[2][8][32];
    sm[0][wid][lane] = v;
    sm[1][wid][lane] = make_float4(v.x * v.x, v.y * v.y, v.z * v.z, v.w * v.w);
    __syncthreads();
    if (threadIdx.x < 128) {
        const int a  = threadIdx.x >> 6;        // 0 sum, 1 sumsq
        const int hh = (threadIdx.x >> 5) & 1;  // half
        const int l  = threadIdx.x & 31;
        float4 r = make_float4(0.f, 0.f, 0.f, 0.f);
#pragma unroll
        for (int w = hh; w < 8; w += 2) {
            float4 u = sm[a][w][l];
            r.x += u.x; r.y += u.y; r.z += u.z; r.w += u.w;
        }
        float* bp = &g_bnp[blockIdx.x & (NBNP - 1)]
                          [A.bnoff + a * 256 + hh * 128 + 4 * l];
        red4(bp, r);
    }
}

// ---------------- BN stats -> per-channel affine -----------------------------
__global__ __launch_bounds__(512) void k_bnstats(
    const float* __restrict__ gamma, const float* __restrict__ beta)
{
    int t = threadIdx.x;
    int c = t & 255;
    int which = t >> 8;
    float sum = 0.f, sq = 0.f;
#pragma unroll
    for (int p = 0; p < NBNP; p++) {
        sum += g_bnp[p][which * 512 + c];
        sq  += g_bnp[p][which * 512 + 256 + c];
    }
    const float invN = 1.f / 100000.f;
    float mean = sum * invN;
    float var  = sq * invN - mean * mean;
    float scale = gamma[c] * rsqrtf(var + 1e-5f);
    g_bn[which * 512 + c]       = scale;
    g_bn[which * 512 + 256 + c] = beta[c] - mean * scale;
}

// ---------------- classifier --------------------------------------------------
__global__ __launch_bounds__(256) void k_classify(
    const int* __restrict__ eli, float* __restrict__ out)
{
    __shared__ float bn[1024];
    int t = threadIdx.x;
#pragma unroll
    for (int k = 0; k < 4; k++) bn[t + 256 * k] = g_bn[t + 256 * k];
    __syncthreads();
    int e = blockIdx.x * 8 + (t >> 5);
    int lane = t & 31;
    if (e >= NLAB) return;
    int i = eli[e];
    int j = eli[NLAB + e];
    const float4* zr = (const float4*)(g_acc_req + (size_t)i * CC);
    const float4* zc = (const float4*)(g_acc_code + (size_t)j * CC);
    float4 a0 = zr[lane], a1 = zr[lane + 32];
    float4 b0 = zc[lane], b1 = zc[lane + 32];
    int c0 = 4 * lane, c1 = 128 + 4 * lane;
    float dot = 0.f;
#pragma unroll
    for (int k = 0; k < 4; k++) {
        float ya = (&a0.x)[k] * bn[c0 + k] + bn[256 + c0 + k];
        float yb = (&b0.x)[k] * bn[512 + c0 + k] + bn[768 + c0 + k];
        dot += ya * yb;
    }
#pragma unroll
    for (int k = 0; k < 4; k++) {
        float ya = (&a1.x)[k] * bn[c1 + k] + bn[256 + c1 + k];
        float yb = (&b1.x)[k] * bn[512 + c1 + k] + bn[768 + c1 + k];
        dot += ya * yb;
    }
#pragma unroll
    for (int o = 16; o >= 1; o >>= 1) dot += __shfl_xor_sync(0xffffffffu, dot, o);
    if (lane == 0) out[e] = 1.f / (1.f + __expf(-dot));
}

// ---------------- host -------------------------------------------------------
template <class T>
static T* getsym(const void* sym) {
    void* p = nullptr;
    cudaGetSymbolAddress(&p, sym);
    return (T*)p;
}

extern "C" void kernel_launch(void* const* d_in, const int* in_sizes, int n_in,
                              void* d_out, int out_size)
{
    const float* x_req      = (const float*)d_in[0];
    const float* x_code     = (const float*)d_in[1];
    const int*   e_rc       = (const int*)d_in[2];
    const int*   e_cr       = (const int*)d_in[3];
    const int*   eli        = (const int*)d_in[4];
    const float* W_req      = (const float*)d_in[5];
    const float* b_req      = (const float*)d_in[6];
    const float* W_code     = (const float*)d_in[7];
    const float* b_code     = (const float*)d_in[8];
    const float* att_src_rc = (const float*)d_in[9];
    const float* att_dst_rc = (const float*)d_in[10];
    const float* att_src_cr = (const float*)d_in[11];
    const float* att_dst_cr = (const float*)d_in[12];
    // d_in[13..15] (k_W, k_b, q) are dead: semantic attention over one metapath.
    const float* gamma      = (const float*)d_in[16];
    const float* beta       = (const float*)d_in[17];
    float* out = (float*)d_out;

    float* h_req    = getsym<float>(g_h_req);
    float* h_code   = getsym<float>(g_h_code);
    float* acc_req  = getsym<float>(g_acc_req);
    float* acc_code = getsym<float>(g_acc_code);
    float* as_rc    = getsym<float>(g_as_rc);
    float* ad_rc    = getsym<float>(g_ad_rc);
    float* as_cr    = getsym<float>(g_as_cr);
    float* ad_cr    = getsym<float>(g_ad_cr);
    float* deg      = getsym<float>(g_deg);
    float* bnp      = getsym<float>(g_bnp);
    float* cursor   = getsym<float>(g_cursor);

    // ---- fork a non-blocking side stream for the CSR build (runs under GEMM).
    // kernel_launch is invoked only for the correctness run + graph capture, so
    // creating (and intentionally not destroying) these handles is cheap and
    // keeps per-call work identical. NonBlocking exempts the side stream from
    // legacy-stream implicit sync; event fork/join makes the capture a DAG.
    cudaStream_t s2;
    cudaEvent_t evFork, evJoin;
    cudaStreamCreateWithFlags(&s2, cudaStreamNonBlocking);
    cudaEventCreateWithFlags(&evFork, cudaEventDisableTiming);
    cudaEventCreateWithFlags(&evJoin, cudaEventDisableTiming);

    cudaEventRecord(evFork, 0);
    cudaStreamWaitEvent(s2, evFork, 0);

    // ---- side stream: zero deg/cursor + CSR build ----
    k_zero<<<(2 * NNODE / 4 + 255) / 256, 256, 0, s2>>>((float4*)deg, 2 * NNODE / 4);
    k_zero<<<1, 256, 0, s2>>>((float4*)cursor, 1);
    dim3 hgrid((NE + 255) / 256, 2);
    k_hist<<<hgrid, 256, 0, s2>>>(e_rc, e_cr);
    dim3 agrid2((NNODE + 255) / 256, 2);
    k_alloc<<<agrid2, 256, 0, s2>>>();
    k_permute<<<hgrid, 256, 0, s2>>>(e_rc, e_cr);
    cudaEventRecord(evJoin, s2);

    // ---- main stream: bnp zero + bf16x3 tensor-core projections ----
    k_zero<<<(NBNP * 1024 / 4 + 255) / 256, 256>>>((float4*)bnp, NBNP * 1024 / 4);

    GemmArgs gr{ x_req,  W_req,  b_req,  h_req,  att_src_rc, att_dst_cr, as_rc, ad_cr };
    GemmArgs gc{ x_code, W_code, b_code, h_code, att_dst_rc, att_src_cr, ad_rc, as_cr };
    cudaFuncSetAttribute(k_gemm_mma, cudaFuncAttributeMaxDynamicSharedMemorySize,
                         SMEM_GEMM_TOTAL);
    dim3 ggrid((NNODE + MTILE - 1) / MTILE, 2);
    k_gemm_mma<<<ggrid, 512, SMEM_GEMM_TOTAL>>>(gr, gc);

    // ---- join: agg needs both CSR (side) and h/attdots (main) ----
    cudaStreamWaitEvent(0, evJoin, 0);

    // ---- CSR aggregate (2 warps/dst, batched prefetch, both types concurrent) ----
    AggArgs a0{ as_rc, ad_rc, h_req,  acc_code, 512 };
    AggArgs a1{ as_cr, ad_cr, h_code, acc_req,  0   };
    dim3 agrid(NNODE / 4, 2);
    k_agg<<<agrid, 256>>>(a0, a1);

    k_bnstats<<<1, 512>>>(gamma, beta);

    k_classify<<<(NLAB + 7) / 8, 256>>>(eli, out);
}